// round 1
// baseline (speedup 1.0000x reference)
#include <cuda_runtime.h>
#include <math.h>

#define NN   100000
#define EE   1200000
#define HH   64
#define EMBD 100
#define BB   4096

// ---------------- scratch (device globals; no allocation allowed) ----------
__device__ float g_h  [NN * HH];
__device__ float g_hm [NN * HH];
__device__ float g_agg[NN * HH];
__device__ float g_cat[BB * 2 * HH];
__device__ float g_hid[BB * HH];
__device__ float g_loss;

// ---------------- projection: h[n] = emb_table[ind[n]] @ Wp + bp ------------
__global__ __launch_bounds__(256) void proj_kernel(
    const float* __restrict__ emb, const int* __restrict__ ind,
    const float* __restrict__ Wp,  const float* __restrict__ bp)
{
    const int j   = threadIdx.x & 63;
    const int grp = threadIdx.x >> 6;      // 4 nodes per block-iteration
    float wc[EMBD];
#pragma unroll
    for (int k = 0; k < EMBD; k++) wc[k] = Wp[k * HH + j];
    const float bj = bp[j];

    __shared__ __align__(16) float s_e[4][EMBD];
    const int ntiles = (NN + 3) / 4;
    for (int tile = blockIdx.x; tile < ntiles; tile += gridDim.x) {
        const int node = tile * 4 + grp;
        __syncthreads();
        if (node < NN) {
            const int row = ind[node];
            for (int k = j; k < EMBD; k += 64) s_e[grp][k] = emb[row * EMBD + k];
        }
        __syncthreads();
        if (node < NN) {
            float acc = bj;
#pragma unroll
            for (int k = 0; k < EMBD; k += 4) {
                const float4 v = *reinterpret_cast<const float4*>(&s_e[grp][k]);
                acc = fmaf(v.x, wc[k + 0], acc);
                acc = fmaf(v.y, wc[k + 1], acc);
                acc = fmaf(v.z, wc[k + 2], acc);
                acc = fmaf(v.w, wc[k + 3], acc);
            }
            g_h[node * HH + j] = acc;
        }
    }
}

// ------------- message precompute: hm = h @ Wm + bm ; agg = 0 --------------
// (bm is added per-edge in the reference, but since agg = sum_edges(hm[src]),
//  folding bm into hm before the gather is exactly equivalent.)
__global__ __launch_bounds__(256) void msg_kernel(
    const float* __restrict__ Wm, const float* __restrict__ bm)
{
    const int j   = threadIdx.x & 63;
    const int grp = threadIdx.x >> 6;
    float wc[HH];
#pragma unroll
    for (int k = 0; k < HH; k++) wc[k] = Wm[k * HH + j];
    const float bj = bm[j];

    __shared__ __align__(16) float s_h[4][HH];
    const int ntiles = (NN + 3) / 4;
    for (int tile = blockIdx.x; tile < ntiles; tile += gridDim.x) {
        const int node = tile * 4 + grp;
        __syncthreads();
        if (node < NN) s_h[grp][j] = g_h[node * HH + j];
        __syncthreads();
        if (node < NN) {
            float acc = bj;
#pragma unroll
            for (int k = 0; k < HH; k += 4) {
                const float4 v = *reinterpret_cast<const float4*>(&s_h[grp][k]);
                acc = fmaf(v.x, wc[k + 0], acc);
                acc = fmaf(v.y, wc[k + 1], acc);
                acc = fmaf(v.z, wc[k + 2], acc);
                acc = fmaf(v.w, wc[k + 3], acc);
            }
            g_hm [node * HH + j] = acc;
            g_agg[node * HH + j] = 0.0f;
        }
    }
}

// ------------- scatter-add: agg[tgt] += hm[src] over all edges -------------
// 16 threads per edge, one float4 each; vector reduction (no return value).
__global__ __launch_bounds__(256) void scatter_kernel(const int* __restrict__ adj)
{
    const int idx = blockIdx.x * 256 + threadIdx.x;   // < EE*16 = 19.2M
    const int e = idx >> 4;
    const int q = idx & 15;
    const int src = adj[2 * e];
    const int tgt = adj[2 * e + 1];
    const float4 v = *reinterpret_cast<const float4*>(g_hm + src * HH + q * 4);
    float* dst = g_agg + tgt * HH + q * 4;
    asm volatile("red.global.add.v4.f32 [%0], {%1,%2,%3,%4};"
                 :: "l"(dst), "f"(v.x), "f"(v.y), "f"(v.z), "f"(v.w)
                 : "memory");
}

// ---------------- GRU cell over all nodes (in-place on g_h) ----------------
__global__ __launch_bounds__(192, 2) void gru_kernel(
    const float* __restrict__ Wih, const float* __restrict__ Whh,
    const float* __restrict__ bih, const float* __restrict__ bhh)
{
    const int j = threadIdx.x;               // 0..191 : one gate column
    float wi[HH], wh[HH];
#pragma unroll
    for (int k = 0; k < HH; k++) {
        wi[k] = Wih[k * 192 + j];
        wh[k] = Whh[k * 192 + j];
    }
    const float bi = bih[j], bh = bhh[j];

    const int T = 6;                         // nodes per tile
    __shared__ __align__(16) float s_x[T * HH];
    __shared__ __align__(16) float s_h[T * HH];
    __shared__ float s_gi[T * 192];
    __shared__ float s_gh[T * 192];

    const int ntiles = (NN + T - 1) / T;
    for (int tile = blockIdx.x; tile < ntiles; tile += gridDim.x) {
        const int base = tile * T;
        const int cnt  = min(T, NN - base);
        __syncthreads();
        for (int i = j; i < cnt * HH; i += 192) {
            s_x[i] = g_agg[base * HH + i];
            s_h[i] = g_h  [base * HH + i];
        }
        __syncthreads();
        for (int t = 0; t < cnt; t++) {
            float ai = bi, ah = bh;
            const float* xr = s_x + t * HH;
            const float* hr = s_h + t * HH;
#pragma unroll
            for (int k = 0; k < HH; k += 4) {
                const float4 x4 = *reinterpret_cast<const float4*>(xr + k);
                const float4 h4 = *reinterpret_cast<const float4*>(hr + k);
                ai = fmaf(x4.x, wi[k + 0], ai);
                ah = fmaf(h4.x, wh[k + 0], ah);
                ai = fmaf(x4.y, wi[k + 1], ai);
                ah = fmaf(h4.y, wh[k + 1], ah);
                ai = fmaf(x4.z, wi[k + 2], ai);
                ah = fmaf(h4.z, wh[k + 2], ah);
                ai = fmaf(x4.w, wi[k + 3], ai);
                ah = fmaf(h4.w, wh[k + 3], ah);
            }
            s_gi[t * 192 + j] = ai;
            s_gh[t * 192 + j] = ah;
        }
        __syncthreads();
        for (int o = j; o < cnt * HH; o += 192) {
            const int t = o >> 6, c = o & 63;
            const float r = 1.0f / (1.0f + __expf(-(s_gi[t*192 + c]       + s_gh[t*192 + c])));
            const float z = 1.0f / (1.0f + __expf(-(s_gi[t*192 + 64 + c]  + s_gh[t*192 + 64 + c])));
            float nx = s_gi[t*192 + 128 + c] + r * s_gh[t*192 + 128 + c];
            nx = fminf(fmaxf(nx, -15.0f), 15.0f);
            const float e2 = __expf(-2.0f * nx);
            const float n  = (1.0f - e2) / (1.0f + e2);
            g_h[base * HH + o] = (1.0f - z) * n + z * s_h[o];
        }
    }
}

// ---------------- gather propagated nodes into concat buffer ---------------
__global__ void gather_kernel(const int* __restrict__ prop, int off)
{
    const int i = blockIdx.x * blockDim.x + threadIdx.x;
    if (i >= BB * HH) return;
    const int b = i >> 6, j = i & 63;
    g_cat[b * (2 * HH) + off + j] = g_h[prop[b] * HH + j];
}

// ---------------- hidden = relu(cat @ W1 + b1) -----------------------------
__global__ __launch_bounds__(256) void hidden_kernel(
    const float* __restrict__ W1, const float* __restrict__ b1)
{
    const int j   = threadIdx.x & 63;
    const int grp = threadIdx.x >> 6;
    float wc[2 * HH];
#pragma unroll
    for (int k = 0; k < 2 * HH; k++) wc[k] = W1[k * HH + j];
    const float bj = b1[j];

    __shared__ __align__(16) float s_c[4][2 * HH];
    const int ntiles = BB / 4;
    for (int tile = blockIdx.x; tile < ntiles; tile += gridDim.x) {
        const int b = tile * 4 + grp;
        __syncthreads();
        s_c[grp][j]      = g_cat[b * 128 + j];
        s_c[grp][j + 64] = g_cat[b * 128 + j + 64];
        __syncthreads();
        float acc = bj;
#pragma unroll
        for (int k = 0; k < 2 * HH; k += 4) {
            const float4 v = *reinterpret_cast<const float4*>(&s_c[grp][k]);
            acc = fmaf(v.x, wc[k + 0], acc);
            acc = fmaf(v.y, wc[k + 1], acc);
            acc = fmaf(v.z, wc[k + 2], acc);
            acc = fmaf(v.w, wc[k + 3], acc);
        }
        g_hid[b * HH + j] = fmaxf(acc, 0.0f);
    }
}

// ---------------- head: z, probs, loss -------------------------------------
__global__ void zero_loss_kernel() { g_loss = 0.0f; }

__global__ void head_kernel(const float* __restrict__ W2, const float* __restrict__ b2,
                            const int* __restrict__ labels, float* __restrict__ out)
{
    const int warp = (blockIdx.x * blockDim.x + threadIdx.x) >> 5;
    const int lane = threadIdx.x & 31;
    if (warp >= BB) return;
    float acc = fmaf(g_hid[warp * HH + lane],      W2[lane],      0.0f);
    acc       = fmaf(g_hid[warp * HH + lane + 32], W2[lane + 32], acc);
#pragma unroll
    for (int s = 16; s; s >>= 1) acc += __shfl_xor_sync(0xffffffffu, acc, s);
    if (lane == 0) {
        const float z = acc + b2[0];
        out[warp] = 1.0f / (1.0f + __expf(-z));
        const float y = (float)labels[warp];
        const float t = (y > 0.5f) ? -z : z;           // y*sp(-z)+(1-y)*sp(z)
        const float sp = fmaxf(t, 0.0f) + log1pf(__expf(-fabsf(t)));
        atomicAdd(&g_loss, sp);
    }
}

__global__ void finalize_kernel(float* __restrict__ out)
{
    out[BB] = g_loss * (1.0f / (float)BB);
}

// ---------------------------------------------------------------------------
extern "C" void kernel_launch(void* const* d_in, const int* in_sizes, int n_in,
                              void* d_out, int out_size)
{
    const int*   emb_ind[2] = {(const int*)d_in[0],  (const int*)d_in[1]};
    const int*   adj[2]     = {(const int*)d_in[2],  (const int*)d_in[3]};
    const int*   prop[2]    = {(const int*)d_in[4],  (const int*)d_in[5]};
    const int*   labels     =  (const int*)d_in[6];
    const float* emb_table  =  (const float*)d_in[7];
    const float* Wp         =  (const float*)d_in[8];
    const float* bp         =  (const float*)d_in[9];
    const float* Wm[2]  = {(const float*)d_in[10], (const float*)d_in[16]};
    const float* bm[2]  = {(const float*)d_in[11], (const float*)d_in[17]};
    const float* Wih[2] = {(const float*)d_in[12], (const float*)d_in[18]};
    const float* Whh[2] = {(const float*)d_in[13], (const float*)d_in[19]};
    const float* bih[2] = {(const float*)d_in[14], (const float*)d_in[20]};
    const float* bhh[2] = {(const float*)d_in[15], (const float*)d_in[21]};
    const float* W1 = (const float*)d_in[22];
    const float* b1 = (const float*)d_in[23];
    const float* W2 = (const float*)d_in[24];
    const float* b2 = (const float*)d_in[25];
    float* out = (float*)d_out;

    for (int g = 0; g < 2; g++) {
        proj_kernel<<<2048, 256>>>(emb_table, emb_ind[g], Wp, bp);
        for (int l = 0; l < 2; l++) {
            for (int t = 0; t < 3; t++) {
                msg_kernel<<<2048, 256>>>(Wm[l], bm[l]);
                scatter_kernel<<<(EE * 16) / 256, 256>>>(adj[g]);
                gru_kernel<<<2048, 192>>>(Wih[l], Whh[l], bih[l], bhh[l]);
            }
        }
        gather_kernel<<<(BB * HH + 255) / 256, 256>>>(prop[g], g * HH);
    }
    hidden_kernel<<<512, 256>>>(W1, b1);
    zero_loss_kernel<<<1, 1>>>();
    head_kernel<<<(BB * 32 + 255) / 256, 256>>>(W2, b2, labels, out);
    finalize_kernel<<<1, 1>>>(out);
    (void)in_sizes; (void)n_in; (void)out_size;
}